// round 15
// baseline (speedup 1.0000x reference)
#include <cuda_runtime.h>
#include <cuda_fp16.h>
#include <math.h>
#include <stdint.h>

#define BATCH   8
#define NTRAIN  2048
#define MTEST   1024
#define DIN     512
#define DHEAD   64
#define NHEADS  6
#define DATTN   384
#define NCLASS  512

// ---------------- scratch (__device__ globals; no runtime allocation) ----------------
__device__ __half  g_q[BATCH * MTEST * DATTN];                  // fp16, pre-scaled by log2e/8
__device__ __half  g_k[BATCH * NTRAIN * DATTN];                 // fp16, class-sorted
__device__ __half  g_wt[2 * DATTN * DIN];                       // Wk^T, Wq^T fp16 [out][in]
__device__ int     g_rank[BATCH * NTRAIN];                      // natural n -> sorted pos
__device__ int     g_cls[BATCH * NTRAIN];                       // sorted class per position
__device__ __half2 g_part_h[NHEADS * BATCH * MTEST * NCLASS / 2]; // 48 MB fp16 partials

// ---------------- helpers ----------------
__device__ __forceinline__ void cp_async16(void* smem_dst, const void* gmem_src) {
    uint32_t d = (uint32_t)__cvta_generic_to_shared(smem_dst);
    asm volatile("cp.async.cg.shared.global [%0], [%1], 16;" :: "r"(d), "l"(gmem_src));
}
__device__ __forceinline__ void cp_async_commit() { asm volatile("cp.async.commit_group;"); }
__device__ __forceinline__ void cp_async_wait0()  { asm volatile("cp.async.wait_group 0;"); }

// fp16 m16n8k16 mma, f32 accum; g=lane>>2, t=lane&3
__device__ __forceinline__ void mma_f16(float& c0, float& c1, float& c2, float& c3,
                                        uint32_t a0, uint32_t a1, uint32_t a2, uint32_t a3,
                                        uint32_t b0, uint32_t b1) {
    asm volatile("mma.sync.aligned.m16n8k16.row.col.f32.f16.f16.f32 "
                 "{%0,%1,%2,%3}, {%4,%5,%6,%7}, {%8,%9}, {%0,%1,%2,%3};"
                 : "+f"(c0), "+f"(c1), "+f"(c2), "+f"(c3)
                 : "r"(a0), "r"(a1), "r"(a2), "r"(a3), "r"(b0), "r"(b1));
}

// two exp2 in one MUFU op; returns packed f16x2 (lo=2^lo, hi=2^hi)
__device__ __forceinline__ uint32_t ex2_f16x2(float lo, float hi) {
    __half2 h = __floats2half2_rn(lo, hi);
    uint32_t x = *(uint32_t*)&h, r;
    asm("ex2.approx.f16x2 %0, %1;" : "=r"(r) : "r"(x));
    return r;
}

// ---------------- kernel 0: transpose+convert W to fp16 [out][in] ----------------
__global__ void prep_kernel(const float* __restrict__ Wq, const float* __restrict__ Wk)
{
    int bx = blockIdx.x;                 // 0..767
    int which = bx / DATTN;              // 0 = Wk, 1 = Wq
    int o = bx - which * DATTN;
    const float* W = which ? Wq : Wk;    // gmem layout [in=512][out=384]
    __half* dst = g_wt + (size_t)which * DATTN * DIN + (size_t)o * DIN;
    for (int in = threadIdx.x; in < DIN; in += blockDim.x)
        dst[in] = __float2half(W[(size_t)in * DATTN + o]);
}

// ---------------- kernel 1: counting sort of keys by class, per batch ----------------
__global__ void sort_kernel(const int* __restrict__ targets)
{
    __shared__ int cnt[NCLASS];
    __shared__ int off[NCLASS];
    const int b   = blockIdx.x;
    const int tid = threadIdx.x;             // 512 threads

    cnt[tid] = 0;
    __syncthreads();
    for (int n = tid; n < NTRAIN; n += 512)
        atomicAdd(&cnt[targets[b * NTRAIN + n]], 1);
    __syncthreads();
    if (tid == 0) {
        int s = 0;
        for (int c = 0; c < NCLASS; c++) { off[c] = s; s += cnt[c]; }
    }
    __syncthreads();
    for (int n = tid; n < NTRAIN; n += 512) {
        int c = targets[b * NTRAIN + n];
        int r = atomicAdd(&off[c], 1);
        g_rank[b * NTRAIN + n] = r;
        g_cls [b * NTRAIN + r] = c;
    }
}

// ---------------- kernel 2: merged fp16 projections  Y = X @ W + bias ----------------
__global__ __launch_bounds__(256, 2) void proj_kernel(
    const float* __restrict__ train, const float* __restrict__ test,
    const float* __restrict__ bq, const float* __restrict__ bk)
{
    __shared__ __align__(128) __half Xs[128 * 64];
    __shared__ __align__(128) __half Ws[128 * 64];

    const int bx = blockIdx.x;
    const int flag_k = (bx < 128) ? 1 : 0;
    const float* X    = flag_k ? train : test;
    const __half* Wt  = g_wt + (flag_k ? 0 : (size_t)DATTN * DIN);
    const float* bias = flag_k ? bk : bq;
    __half* __restrict__ Y = flag_k ? g_k : g_q;
    // q carries 1/sqrt(64) AND log2(e) so attention uses pure 2^x
    const float oscale = flag_k ? 1.0f : (0.125f * 1.44269504088896f);
    const int rm0 = (flag_k ? bx : (bx - 128)) * 128;
    const int bn  = blockIdx.y * 128;

    const int tid  = threadIdx.x;
    const int w    = tid >> 5;
    const int lane = tid & 31;
    const int g    = lane >> 2;
    const int t    = lane & 3;
    const int m_off = (w & 3) * 32;
    const int n_off = (w >> 2) * 64;

    float c[2][8][4];
#pragma unroll
    for (int mt = 0; mt < 2; mt++)
#pragma unroll
        for (int nt = 0; nt < 8; nt++)
#pragma unroll
            for (int i = 0; i < 4; i++) c[mt][nt][i] = 0.f;

    for (int kt = 0; kt < DIN; kt += 64) {
        // W tile: cp.async fp16, swizzled dst
#pragma unroll
        for (int i = 0; i < 4; i++) {
            int idx = tid + i * 256;
            int col = idx >> 3, slot = idx & 7;
            int ps_ = slot ^ (col & 7);
            cp_async16(Ws + col * 64 + ps_ * 8,
                       Wt + (size_t)(bn + col) * DIN + kt + slot * 8);
        }
        cp_async_commit();
        // X tile: LDG fp32 -> cvt fp16 -> swizzled STS.128
#pragma unroll
        for (int i = 0; i < 4; i++) {
            int idx = tid + i * 256;
            int row = idx >> 3, slot = idx & 7;
            const float* src = X + (size_t)(rm0 + row) * DIN + kt + slot * 8;
            float4 v0 = *(const float4*)src;
            float4 v1 = *(const float4*)(src + 4);
            __half2 h0 = __floats2half2_rn(v0.x, v0.y);
            __half2 h1 = __floats2half2_rn(v0.z, v0.w);
            __half2 h2 = __floats2half2_rn(v1.x, v1.y);
            __half2 h3 = __floats2half2_rn(v1.z, v1.w);
            uint4 pk;
            pk.x = *(uint32_t*)&h0; pk.y = *(uint32_t*)&h1;
            pk.z = *(uint32_t*)&h2; pk.w = *(uint32_t*)&h3;
            int ps_ = slot ^ (row & 7);
            *(uint4*)(Xs + row * 64 + ps_ * 8) = pk;
        }
        cp_async_wait0();
        __syncthreads();

#pragma unroll
        for (int kk = 0; kk < 4; kk++) {
            const int s0 = (2 * kk)     ^ g;
            const int s1 = (2 * kk + 1) ^ g;
            uint32_t a[2][4];
#pragma unroll
            for (int mt = 0; mt < 2; mt++) {
                const __half* xr  = Xs + (m_off + mt * 16 + g) * 64;
                const __half* xr2 = Xs + (m_off + mt * 16 + g + 8) * 64;
                a[mt][0] = *(const uint32_t*)(xr  + s0 * 8 + 2 * t);
                a[mt][1] = *(const uint32_t*)(xr2 + s0 * 8 + 2 * t);
                a[mt][2] = *(const uint32_t*)(xr  + s1 * 8 + 2 * t);
                a[mt][3] = *(const uint32_t*)(xr2 + s1 * 8 + 2 * t);
            }
#pragma unroll
            for (int nt = 0; nt < 8; nt++) {
                const __half* wr = Ws + (n_off + nt * 8 + g) * 64;
                uint32_t b0 = *(const uint32_t*)(wr + s0 * 8 + 2 * t);
                uint32_t b1 = *(const uint32_t*)(wr + s1 * 8 + 2 * t);
                mma_f16(c[0][nt][0], c[0][nt][1], c[0][nt][2], c[0][nt][3],
                        a[0][0], a[0][1], a[0][2], a[0][3], b0, b1);
                mma_f16(c[1][nt][0], c[1][nt][1], c[1][nt][2], c[1][nt][3],
                        a[1][0], a[1][1], a[1][2], a[1][3], b0, b1);
            }
        }
        __syncthreads();
    }

#pragma unroll
    for (int mt = 0; mt < 2; mt++) {
        int r0 = rm0 + m_off + mt * 16 + g;
        int r1 = r0 + 8;
        int o0 = r0, o1 = r1;
        if (flag_k) {
            int bb0 = r0 >> 11, bb1 = r1 >> 11;       // NTRAIN = 2048
            o0 = (bb0 << 11) + g_rank[r0];
            o1 = (bb1 << 11) + g_rank[r1];
        }
#pragma unroll
        for (int nt = 0; nt < 8; nt++) {
            int col = bn + n_off + nt * 8 + 2 * t;
            float bv0 = bias[col], bv1 = bias[col + 1];
            __half2 v0 = __floats2half2_rn((c[mt][nt][0] + bv0) * oscale,
                                           (c[mt][nt][1] + bv1) * oscale);
            __half2 v1 = __floats2half2_rn((c[mt][nt][2] + bv0) * oscale,
                                           (c[mt][nt][3] + bv1) * oscale);
            *(__half2*)(Y + (size_t)o0 * DATTN + col) = v0;
            *(__half2*)(Y + (size_t)o1 * DATTN + col) = v1;
        }
    }
}

// ---------------- kernel 3: barrier-free fused attention ----------------
// grid (32 mt, 8 b, 6 h); 512 threads; 64-key tiles (32 iters); 2 CTAs/SM.
// NO shared K: each lane's B-frags come from ONE global K row (L2-resident),
// register double-buffered one tile ahead. NO __syncthreads in the main loop —
// pw is warp-private (double-buffered, one __syncwarp), hist uses atomics whose
// interior-run exclusivity never needed barriers.
#define HSTRIDE   33
#define QS_STRIDE 72
// byte-offset smem layout
#define SMB_PW    0                         // pw 16 x 2 x [16][4] u32 = 8192
#define SMB_QS    8192                      // q [32][72] half         = 4608
#define SMB_HIST  12800                     // hist [512][33] f32      = 67584
#define SMB_ZS    80384                     // invZ[32] f32            =   128
#define SMB_ZPART 80512                     // zpart[8][32] f32        =  1024
#define SMB_CLS   81536                     // cls[2048] int           =  8192
#define SMEM_BYTES 89728

__global__ __launch_bounds__(512, 2) void attn_kernel()
{
    extern __shared__ __align__(1024) char smc[];
    __half*   qs   = (__half*)  (smc + SMB_QS);
    float*    hist = (float*)   (smc + SMB_HIST);
    float*    zs   = (float*)   (smc + SMB_ZS);
    float*    zpart= (float*)   (smc + SMB_ZPART);
    int*      cls  = (int*)     (smc + SMB_CLS);

    const int tid  = threadIdx.x;
    const int mt   = blockIdx.x;
    const int b    = blockIdx.y;
    const int h    = blockIdx.z;
    const int w    = tid >> 5;          // 0..15
    const int lane = tid & 31;
    const int g    = lane >> 2;
    const int t    = lane & 3;
    const int m_off = (w & 1) * 16;     // m16 block
    const int n_oct = w >> 1;           // key octet 0..7
    const int n_off = n_oct * 8;
    uint32_t* pwb = (uint32_t*)(smc + SMB_PW) + w * 128;   // 2 x [16 rows][4 words]

    // sorted class ids for this batch
    for (int i = tid; i < NTRAIN; i += 512) cls[i] = g_cls[b * NTRAIN + i];
    // zero histogram
    for (int i = tid; i < (NCLASS * HSTRIDE) / 4; i += 512)
        *(float4*)(hist + 4 * i) = make_float4(0.f, 0.f, 0.f, 0.f);
    // load q tile (pre-scaled by log2e/8 at projection)
    {
        const __half* src = g_q + ((size_t)(b * MTEST + mt * 32)) * DATTN + h * DHEAD;
#pragma unroll
        for (int s = 0; s < 2; s++) {
            int idx = tid + s * 512;           // 1024 half2 slots
            int r = idx >> 5, c2 = idx & 31;
            uint32_t v = *(const uint32_t*)(src + (size_t)r * DATTN + 2 * c2);
            *(uint32_t*)(qs + r * QS_STRIDE + 2 * c2) = v;
        }
    }

    // this lane's K row pointer (row n_off+g of tile 0) — one 128B line per tile
    const __half* kr = g_k + ((size_t)(b * NTRAIN) + n_off + g) * DATTN + h * DHEAD;

    // prologue: load tile-0 fragments into register buffer 0
    uint32_t bf[2][8];
#pragma unroll
    for (int kk = 0; kk < 4; kk++) {
        bf[0][2 * kk]     = *(const uint32_t*)(kr + kk * 16 + 2 * t);
        bf[0][2 * kk + 1] = *(const uint32_t*)(kr + kk * 16 + 2 * t + 8);
    }

    __syncthreads();      // qs + cls + hist-zero visible; NO more block barriers in loop

    // A fragments of Q (constant across all K tiles)
    uint32_t a[4][4];
#pragma unroll
    for (int kk = 0; kk < 4; kk++) {
        const __half* q0 = qs + (m_off + g) * QS_STRIDE + kk * 16;
        const __half* q1 = qs + (m_off + g + 8) * QS_STRIDE + kk * 16;
        a[kk][0] = *(const uint32_t*)(q0 + 2 * t);
        a[kk][1] = *(const uint32_t*)(q1 + 2 * t);
        a[kk][2] = *(const uint32_t*)(q0 + 2 * t + 8);
        a[kk][3] = *(const uint32_t*)(q1 + 2 * t + 8);
    }

    float rs0 = 0.f, rs1 = 0.f;

    for (int t32 = 0; t32 < 32; t32++) {
        const int nt = t32 << 6;
        const int cur = t32 & 1;

        // issue next tile's fragment loads (independent LDGs; L2-resident K)
        if (t32 + 1 < 32) {
            const __half* nk = kr + (size_t)(nt + 64) * DATTN;
#pragma unroll
            for (int kk = 0; kk < 4; kk++) {
                bf[cur ^ 1][2 * kk]     = *(const uint32_t*)(nk + kk * 16 + 2 * t);
                bf[cur ^ 1][2 * kk + 1] = *(const uint32_t*)(nk + kk * 16 + 2 * t + 8);
            }
        }

        // one n8 block per warp
        {
            float c0 = 0.f, c1 = 0.f, c2 = 0.f, c3 = 0.f;
#pragma unroll
            for (int kk = 0; kk < 4; kk++)
                mma_f16(c0, c1, c2, c3, a[kk][0], a[kk][1], a[kk][2], a[kk][3],
                        bf[cur][2 * kk], bf[cur][2 * kk + 1]);
            // p = 2^(s*log2e) = exp(s): one MUFU per pair, packed fp16x2
            uint32_t p01 = ex2_f16x2(c0, c1);
            uint32_t p23 = ex2_f16x2(c2, c3);
            float2 f01 = __half22float2(*(__half2*)&p01);
            float2 f23 = __half22float2(*(__half2*)&p23);
            rs0 += f01.x + f01.y;
            rs1 += f23.x + f23.y;
            uint32_t* pww = pwb + cur * 64;
            pww[g * 4 + t]       = p01;   // row g, key pair t
            pww[(g + 8) * 4 + t] = p23;   // row g+8
        }
        __syncwarp();

        // warp-local scatter: lane = (row lr, key-half kh): 4-key substrip
        {
            const int lr   = lane & 15;
            const int kh   = lane >> 4;
            const int grow = m_off + lr;
            const int base = nt + n_off + kh * 4;
            const uint32_t* pww = pwb + cur * 64;

            uint2 pv2 = *(const uint2*)(pww + lr * 4 + kh * 2);
            float2 fa = __half22float2(*(__half2*)&pv2.x);
            float2 fb = __half22float2(*(__half2*)&pv2.y);
            float pv[4] = {fa.x, fa.y, fb.x, fb.y};

            int4 cv = *(const int4*)(cls + base);
            int cc[4] = {cv.x, cv.y, cv.z, cv.w};

            float run = 0.f;
            int   rc  = cc[0];
            int   nflush = 0;
#pragma unroll
            for (int i = 0; i < 4; i++) {
                int c = cc[i];
                if (c != rc) {
                    if (nflush == 0) atomicAdd(hist + rc * HSTRIDE + grow, run);
                    else             hist[rc * HSTRIDE + grow] += run;
                    nflush++;
                    rc = c; run = 0.f;
                }
                run += pv[i];
            }
            atomicAdd(hist + rc * HSTRIDE + grow, run);
        }
        // no block sync: pw double buffer + next iteration's __syncwarp order reuse
    }

    // deterministic Z reduction: quad-reduce (over t), per-octet write, tree sum
    rs0 += __shfl_xor_sync(0xffffffffu, rs0, 1);
    rs0 += __shfl_xor_sync(0xffffffffu, rs0, 2);
    rs1 += __shfl_xor_sync(0xffffffffu, rs1, 1);
    rs1 += __shfl_xor_sync(0xffffffffu, rs1, 2);
    if (t == 0) {
        zpart[n_oct * 32 + m_off + g]     = rs0;
        zpart[n_oct * 32 + m_off + 8 + g] = rs1;
    }
    __syncthreads();        // all scatters + zpart visible
    if (tid < 32) {
        float z = 0.f;
#pragma unroll
        for (int j = 0; j < 8; j++) z += zpart[j * 32 + tid];
        zs[tid] = 1.0f / (6.0f * z);
    }
    __syncthreads();

    // write normalized per-head partial as half2 (coalesced)
    __half2* dst = g_part_h + (((size_t)(h * BATCH + b)) * MTEST + mt * 32) * (NCLASS / 2);
    for (int i = tid; i < 32 * (NCLASS / 2); i += 512) {
        int q = i >> 8, c2 = i & 255;
        float z = zs[q];
        float v0 = hist[(2 * c2)     * HSTRIDE + q] * z;
        float v1 = hist[(2 * c2 + 1) * HSTRIDE + q] * z;
        dst[q * (NCLASS / 2) + c2] = __floats2half2_rn(v0, v1);
    }
}

// ---------------- kernel 4: sum heads (fp16 partials) + log, write [M,B,C] ----------------
__global__ void final_kernel(float* __restrict__ out)
{
    int i = blockIdx.x * blockDim.x + threadIdx.x;      // half2 index
    if (i >= (MTEST * BATCH * NCLASS) / 2) return;
    int c2 = i & 255;
    int bm = i >> 8;             // m*8 + b
    int b  = bm & 7;
    int m  = bm >> 3;
    size_t pi = ((size_t)(b * MTEST) + m) * (NCLASS / 2) + c2;
    float vx = 0.f, vy = 0.f;
#pragma unroll
    for (int hh = 0; hh < NHEADS; hh++) {
        float2 p = __half22float2(g_part_h[(size_t)hh * (BATCH * MTEST * NCLASS / 2) + pi]);
        vx += p.x; vy += p.y;
    }
    float2 o;
    o.x = logf(fmaxf(vx, 1e-5f) + 3e-5f);
    o.y = logf(fmaxf(vy, 1e-5f) + 3e-5f);
    *((float2*)out + ((size_t)(m * 8 + b)) * 256 + c2) = o;
}

// ---------------- launch ----------------
extern "C" void kernel_launch(void* const* d_in, const int* in_sizes, int n_in,
                              void* d_out, int out_size)
{
    const float* train   = (const float*)d_in[0];
    const float* test    = (const float*)d_in[1];
    const int*   targets = (const int*)  d_in[2];
    const float* Wq      = (const float*)d_in[3];
    const float* bq      = (const float*)d_in[4];
    const float* Wk      = (const float*)d_in[5];
    const float* bk      = (const float*)d_in[6];
    float* out = (float*)d_out;

    cudaFuncSetAttribute(attn_kernel,
                         cudaFuncAttributeMaxDynamicSharedMemorySize, SMEM_BYTES);

    prep_kernel<<<2 * DATTN, 128>>>(Wq, Wk);
    sort_kernel<<<BATCH, 512>>>(targets);

    proj_kernel<<<dim3(192, DATTN / 128), 256>>>(train, test, bq, bk);

    attn_kernel<<<dim3(MTEST / 32, BATCH, NHEADS), 512, SMEM_BYTES>>>();

    final_kernel<<<(MTEST * BATCH * NCLASS / 2 + 255) / 256, 256>>>(out);
}

// round 16
// speedup vs baseline: 1.9476x; 1.9476x over previous
#include <cuda_runtime.h>
#include <cuda_fp16.h>
#include <math.h>
#include <stdint.h>

#define BATCH   8
#define NTRAIN  2048
#define MTEST   1024
#define DIN     512
#define DHEAD   64
#define NHEADS  6
#define DATTN   384
#define NCLASS  512

// ---------------- scratch (__device__ globals; no runtime allocation) ----------------
__device__ __half  g_q[BATCH * MTEST * DATTN];                  // fp16, pre-scaled by log2e/8
__device__ __half  g_k[BATCH * NTRAIN * DATTN];                 // fp16, class-sorted
__device__ __half  g_wt[2 * DATTN * DIN];                       // Wk^T, Wq^T fp16 [out][in]
__device__ int     g_rank[BATCH * NTRAIN];                      // natural n -> sorted pos
__device__ int     g_cls[BATCH * NTRAIN];                       // sorted class per position
__device__ __half2 g_part_h[NHEADS * BATCH * MTEST * NCLASS / 2]; // 48 MB fp16 partials

// ---------------- helpers ----------------
__device__ __forceinline__ void cp_async16(void* smem_dst, const void* gmem_src) {
    uint32_t d = (uint32_t)__cvta_generic_to_shared(smem_dst);
    asm volatile("cp.async.cg.shared.global [%0], [%1], 16;" :: "r"(d), "l"(gmem_src));
}
__device__ __forceinline__ void cp_async_commit() { asm volatile("cp.async.commit_group;"); }
__device__ __forceinline__ void cp_async_wait0()  { asm volatile("cp.async.wait_group 0;"); }

__device__ __forceinline__ void bar_pair(int id) {
    asm volatile("bar.sync %0, 64;" :: "r"(id) : "memory");
}

// fp16 m16n8k16 mma, f32 accum; g=lane>>2, t=lane&3
__device__ __forceinline__ void mma_f16(float& c0, float& c1, float& c2, float& c3,
                                        uint32_t a0, uint32_t a1, uint32_t a2, uint32_t a3,
                                        uint32_t b0, uint32_t b1) {
    asm volatile("mma.sync.aligned.m16n8k16.row.col.f32.f16.f16.f32 "
                 "{%0,%1,%2,%3}, {%4,%5,%6,%7}, {%8,%9}, {%0,%1,%2,%3};"
                 : "+f"(c0), "+f"(c1), "+f"(c2), "+f"(c3)
                 : "r"(a0), "r"(a1), "r"(a2), "r"(a3), "r"(b0), "r"(b1));
}

// two exp2 in one MUFU op; returns packed f16x2 (lo=2^lo, hi=2^hi)
__device__ __forceinline__ uint32_t ex2_f16x2(float lo, float hi) {
    __half2 h = __floats2half2_rn(lo, hi);
    uint32_t x = *(uint32_t*)&h, r;
    asm("ex2.approx.f16x2 %0, %1;" : "=r"(r) : "r"(x));
    return r;
}

// ---------------- kernel 0: transpose+convert W to fp16 [out][in] ----------------
__global__ void prep_kernel(const float* __restrict__ Wq, const float* __restrict__ Wk)
{
    int bx = blockIdx.x;                 // 0..767
    int which = bx / DATTN;              // 0 = Wk, 1 = Wq
    int o = bx - which * DATTN;
    const float* W = which ? Wq : Wk;    // gmem layout [in=512][out=384]
    __half* dst = g_wt + (size_t)which * DATTN * DIN + (size_t)o * DIN;
    for (int in = threadIdx.x; in < DIN; in += blockDim.x)
        dst[in] = __float2half(W[(size_t)in * DATTN + o]);
}

// ---------------- kernel 1: counting sort of keys by class, per batch ----------------
__global__ void sort_kernel(const int* __restrict__ targets)
{
    __shared__ int cnt[NCLASS];
    __shared__ int off[NCLASS];
    const int b   = blockIdx.x;
    const int tid = threadIdx.x;             // 512 threads

    cnt[tid] = 0;
    __syncthreads();
    for (int n = tid; n < NTRAIN; n += 512)
        atomicAdd(&cnt[targets[b * NTRAIN + n]], 1);
    __syncthreads();
    if (tid == 0) {
        int s = 0;
        for (int c = 0; c < NCLASS; c++) { off[c] = s; s += cnt[c]; }
    }
    __syncthreads();
    for (int n = tid; n < NTRAIN; n += 512) {
        int c = targets[b * NTRAIN + n];
        int r = atomicAdd(&off[c], 1);
        g_rank[b * NTRAIN + n] = r;
        g_cls [b * NTRAIN + r] = c;
    }
}

// ---------------- kernel 2: merged fp16 projections  Y = X @ W + bias ----------------
__global__ __launch_bounds__(256, 2) void proj_kernel(
    const float* __restrict__ train, const float* __restrict__ test,
    const float* __restrict__ bq, const float* __restrict__ bk)
{
    __shared__ __align__(128) __half Xs[128 * 64];
    __shared__ __align__(128) __half Ws[128 * 64];

    const int bx = blockIdx.x;
    const int flag_k = (bx < 128) ? 1 : 0;
    const float* X    = flag_k ? train : test;
    const __half* Wt  = g_wt + (flag_k ? 0 : (size_t)DATTN * DIN);
    const float* bias = flag_k ? bk : bq;
    __half* __restrict__ Y = flag_k ? g_k : g_q;
    // q carries 1/sqrt(64) AND log2(e) so attention uses pure 2^x
    const float oscale = flag_k ? 1.0f : (0.125f * 1.44269504088896f);
    const int rm0 = (flag_k ? bx : (bx - 128)) * 128;
    const int bn  = blockIdx.y * 128;

    const int tid  = threadIdx.x;
    const int w    = tid >> 5;
    const int lane = tid & 31;
    const int g    = lane >> 2;
    const int t    = lane & 3;
    const int m_off = (w & 3) * 32;
    const int n_off = (w >> 2) * 64;

    float c[2][8][4];
#pragma unroll
    for (int mt = 0; mt < 2; mt++)
#pragma unroll
        for (int nt = 0; nt < 8; nt++)
#pragma unroll
            for (int i = 0; i < 4; i++) c[mt][nt][i] = 0.f;

    for (int kt = 0; kt < DIN; kt += 64) {
        // W tile: cp.async fp16, swizzled dst
#pragma unroll
        for (int i = 0; i < 4; i++) {
            int idx = tid + i * 256;
            int col = idx >> 3, slot = idx & 7;
            int ps_ = slot ^ (col & 7);
            cp_async16(Ws + col * 64 + ps_ * 8,
                       Wt + (size_t)(bn + col) * DIN + kt + slot * 8);
        }
        cp_async_commit();
        // X tile: LDG fp32 -> cvt fp16 -> swizzled STS.128
#pragma unroll
        for (int i = 0; i < 4; i++) {
            int idx = tid + i * 256;
            int row = idx >> 3, slot = idx & 7;
            const float* src = X + (size_t)(rm0 + row) * DIN + kt + slot * 8;
            float4 v0 = *(const float4*)src;
            float4 v1 = *(const float4*)(src + 4);
            __half2 h0 = __floats2half2_rn(v0.x, v0.y);
            __half2 h1 = __floats2half2_rn(v0.z, v0.w);
            __half2 h2 = __floats2half2_rn(v1.x, v1.y);
            __half2 h3 = __floats2half2_rn(v1.z, v1.w);
            uint4 pk;
            pk.x = *(uint32_t*)&h0; pk.y = *(uint32_t*)&h1;
            pk.z = *(uint32_t*)&h2; pk.w = *(uint32_t*)&h3;
            int ps_ = slot ^ (row & 7);
            *(uint4*)(Xs + row * 64 + ps_ * 8) = pk;
        }
        cp_async_wait0();
        __syncthreads();

#pragma unroll
        for (int kk = 0; kk < 4; kk++) {
            const int s0 = (2 * kk)     ^ g;
            const int s1 = (2 * kk + 1) ^ g;
            uint32_t a[2][4];
#pragma unroll
            for (int mt = 0; mt < 2; mt++) {
                const __half* xr  = Xs + (m_off + mt * 16 + g) * 64;
                const __half* xr2 = Xs + (m_off + mt * 16 + g + 8) * 64;
                a[mt][0] = *(const uint32_t*)(xr  + s0 * 8 + 2 * t);
                a[mt][1] = *(const uint32_t*)(xr2 + s0 * 8 + 2 * t);
                a[mt][2] = *(const uint32_t*)(xr  + s1 * 8 + 2 * t);
                a[mt][3] = *(const uint32_t*)(xr2 + s1 * 8 + 2 * t);
            }
#pragma unroll
            for (int nt = 0; nt < 8; nt++) {
                const __half* wr = Ws + (n_off + nt * 8 + g) * 64;
                uint32_t b0 = *(const uint32_t*)(wr + s0 * 8 + 2 * t);
                uint32_t b1 = *(const uint32_t*)(wr + s1 * 8 + 2 * t);
                mma_f16(c[0][nt][0], c[0][nt][1], c[0][nt][2], c[0][nt][3],
                        a[0][0], a[0][1], a[0][2], a[0][3], b0, b1);
                mma_f16(c[1][nt][0], c[1][nt][1], c[1][nt][2], c[1][nt][3],
                        a[1][0], a[1][1], a[1][2], a[1][3], b0, b1);
            }
        }
        __syncthreads();
    }

#pragma unroll
    for (int mt = 0; mt < 2; mt++) {
        int r0 = rm0 + m_off + mt * 16 + g;
        int r1 = r0 + 8;
        int o0 = r0, o1 = r1;
        if (flag_k) {
            int bb0 = r0 >> 11, bb1 = r1 >> 11;       // NTRAIN = 2048
            o0 = (bb0 << 11) + g_rank[r0];
            o1 = (bb1 << 11) + g_rank[r1];
        }
#pragma unroll
        for (int nt = 0; nt < 8; nt++) {
            int col = bn + n_off + nt * 8 + 2 * t;
            float bv0 = bias[col], bv1 = bias[col + 1];
            __half2 v0 = __floats2half2_rn((c[mt][nt][0] + bv0) * oscale,
                                           (c[mt][nt][1] + bv1) * oscale);
            __half2 v1 = __floats2half2_rn((c[mt][nt][2] + bv0) * oscale,
                                           (c[mt][nt][3] + bv1) * oscale);
            *(__half2*)(Y + (size_t)o0 * DATTN + col) = v0;
            *(__half2*)(Y + (size_t)o1 * DATTN + col) = v1;
        }
    }
}

// ---------------- kernel 3: fused attention, pairwise-synced ----------------
// grid (32 mt, 8 b, 6 h); 512 threads; 64-key tiles (32 iters); 2 CTAs/SM.
// K tile rows n are loaded by thread tid = 8n+slot, i.e. warp w loads rows
// 4w..4w+3 — exactly the two warps of octet o=w>>1 cover rows 8o..8o+7, the
// ONLY rows they read. So per-tile sync is a 64-thread named barrier per pair,
// not a block barrier; warp pairs drift freely.
#define HSTRIDE   33
#define KS_STRIDE 72                        // halves per K row
#define KS_BUF    (64 * KS_STRIDE)          // 4608 halves = 9216 B per buffer
#define QS_STRIDE 72
// byte-offset smem layout
#define SMB_KS    0                         // 2 x 9216             = 18432
#define SMB_PW    18432                     // pw 16 x [16][4] u32  =  4096
#define SMB_QS    22528                     // q [32][72] half      =  4608
#define SMB_HIST  27136                     // hist [512][33] f32   = 67584
#define SMB_ZS    94720                     // invZ[32] f32         =   128
#define SMB_ZPART 94848                     // zpart[8][32] f32     =  1024
#define SMB_CLS   95872                     // cls[2048] int        =  8192
#define SMEM_BYTES 104064

__global__ __launch_bounds__(512, 2) void attn_kernel()
{
    extern __shared__ __align__(1024) char smc[];
    __half*   ks   = (__half*)  (smc + SMB_KS);
    __half*   qs   = (__half*)  (smc + SMB_QS);
    float*    hist = (float*)   (smc + SMB_HIST);
    float*    zs   = (float*)   (smc + SMB_ZS);
    float*    zpart= (float*)   (smc + SMB_ZPART);
    int*      cls  = (int*)     (smc + SMB_CLS);

    const int tid  = threadIdx.x;
    const int mt   = blockIdx.x;
    const int b    = blockIdx.y;
    const int h    = blockIdx.z;
    const int w    = tid >> 5;          // 0..15
    const int lane = tid & 31;
    const int g    = lane >> 2;
    const int t    = lane & 3;
    const int m_off = (w & 1) * 16;     // m16 block
    const int n_oct = w >> 1;           // key octet 0..7
    const int n_off = n_oct * 8;
    const int bar_id = 1 + n_oct;       // named barrier per warp-pair (ids 1..8)
    uint32_t* pww = (uint32_t*)(smc + SMB_PW) + w * 64;   // [16 rows][4 words]

    const __half* ksrc = g_k + ((size_t)(b * NTRAIN)) * DATTN + h * DHEAD;
    const int ld_n    = tid >> 3;       // my K row (= 4w + lane>>3)
    const int ld_slot = tid & 7;

    // prologue: issue K tile 0 (1 slot per thread; warp loads its pair's rows)
    cp_async16(ks + ld_n * KS_STRIDE + ld_slot * 8,
               ksrc + (size_t)ld_n * DATTN + ld_slot * 8);
    cp_async_commit();

    // sorted class ids for this batch
    for (int i = tid; i < NTRAIN; i += 512) cls[i] = g_cls[b * NTRAIN + i];
    // zero histogram
    for (int i = tid; i < (NCLASS * HSTRIDE) / 4; i += 512)
        *(float4*)(hist + 4 * i) = make_float4(0.f, 0.f, 0.f, 0.f);
    // load q tile (pre-scaled by log2e/8 at projection)
    {
        const __half* src = g_q + ((size_t)(b * MTEST + mt * 32)) * DATTN + h * DHEAD;
#pragma unroll
        for (int s = 0; s < 2; s++) {
            int idx = tid + s * 512;           // 1024 half2 slots
            int r = idx >> 5, c2 = idx & 31;
            uint32_t v = *(const uint32_t*)(src + (size_t)r * DATTN + 2 * c2);
            *(uint32_t*)(qs + r * QS_STRIDE + 2 * c2) = v;
        }
    }
    __syncthreads();      // qs + cls + hist-zero visible (once, before the loop)

    // A fragments of Q (constant across all K tiles)
    uint32_t a[4][4];
#pragma unroll
    for (int kk = 0; kk < 4; kk++) {
        const __half* q0 = qs + (m_off + g) * QS_STRIDE + kk * 16;
        const __half* q1 = qs + (m_off + g + 8) * QS_STRIDE + kk * 16;
        a[kk][0] = *(const uint32_t*)(q0 + 2 * t);
        a[kk][1] = *(const uint32_t*)(q1 + 2 * t);
        a[kk][2] = *(const uint32_t*)(q0 + 2 * t + 8);
        a[kk][3] = *(const uint32_t*)(q1 + 2 * t + 8);
    }

    float rs0 = 0.f, rs1 = 0.f;

    for (int t32 = 0; t32 < 32; t32++) {
        const int nt = t32 << 6;
        cp_async_wait0();                // my tile-t32 slot landed
        bar_pair(bar_id);                // partner's slots landed; partner consumed t32-1

        // issue next tile (overlaps compute; buffer (t32+1)&1 free per pair-barrier)
        if (t32 + 1 < 32) {
            const __half* nsrc = ksrc + (size_t)(nt + 64 + ld_n) * DATTN;
            __half* nbuf = ks + ((t32 + 1) & 1) * KS_BUF;
            cp_async16(nbuf + ld_n * KS_STRIDE + ld_slot * 8,
                       nsrc + ld_slot * 8);
            cp_async_commit();
        }

        const __half* kb = ks + (t32 & 1) * KS_BUF;

        // one n8 block per warp; B-frag half2 reads conflict-free (banks 4g+t)
        {
            const __half* kr = kb + (n_off + g) * KS_STRIDE;
            float c0 = 0.f, c1 = 0.f, c2 = 0.f, c3 = 0.f;
#pragma unroll
            for (int kk = 0; kk < 4; kk++) {
                uint32_t b0 = *(const uint32_t*)(kr + kk * 16 + 2 * t);
                uint32_t b1 = *(const uint32_t*)(kr + kk * 16 + 2 * t + 8);
                mma_f16(c0, c1, c2, c3, a[kk][0], a[kk][1], a[kk][2], a[kk][3], b0, b1);
            }
            // p = 2^(s*log2e) = exp(s): one MUFU per pair, packed fp16x2
            uint32_t p01 = ex2_f16x2(c0, c1);
            uint32_t p23 = ex2_f16x2(c2, c3);
            float2 f01 = __half22float2(*(__half2*)&p01);
            float2 f23 = __half22float2(*(__half2*)&p23);
            rs0 += f01.x + f01.y;
            rs1 += f23.x + f23.y;
            pww[g * 4 + t]       = p01;   // row g, key pair t
            pww[(g + 8) * 4 + t] = p23;   // row g+8
        }
        __syncwarp();

        // warp-local scatter: lane = (row lr, key-half kh): 4-key substrip
        {
            const int lr   = lane & 15;
            const int kh   = lane >> 4;
            const int grow = m_off + lr;
            const int base = nt + n_off + kh * 4;

            uint2 pv2 = *(const uint2*)(pww + lr * 4 + kh * 2);
            float2 fa = __half22float2(*(__half2*)&pv2.x);
            float2 fb = __half22float2(*(__half2*)&pv2.y);
            float pv[4] = {fa.x, fa.y, fb.x, fb.y};

            int4 cv = *(const int4*)(cls + base);
            int cc[4] = {cv.x, cv.y, cv.z, cv.w};

            float run = 0.f;
            int   rc  = cc[0];
            int   nflush = 0;
#pragma unroll
            for (int i = 0; i < 4; i++) {
                int c = cc[i];
                if (c != rc) {
                    if (nflush == 0) atomicAdd(hist + rc * HSTRIDE + grow, run);
                    else             hist[rc * HSTRIDE + grow] += run;
                    nflush++;
                    rc = c; run = 0.f;
                }
                run += pv[i];
            }
            atomicAdd(hist + rc * HSTRIDE + grow, run);
        }
        __syncwarp();    // protect pw from next tile's overwrite
    }

    // deterministic Z reduction: quad-reduce (over t), per-octet write, tree sum
    rs0 += __shfl_xor_sync(0xffffffffu, rs0, 1);
    rs0 += __shfl_xor_sync(0xffffffffu, rs0, 2);
    rs1 += __shfl_xor_sync(0xffffffffu, rs1, 1);
    rs1 += __shfl_xor_sync(0xffffffffu, rs1, 2);
    if (t == 0) {
        zpart[n_oct * 32 + m_off + g]     = rs0;
        zpart[n_oct * 32 + m_off + 8 + g] = rs1;
    }
    __syncthreads();     // all scatters + zpart visible
    if (tid < 32) {
        float z = 0.f;
#pragma unroll
        for (int j = 0; j < 8; j++) z += zpart[j * 32 + tid];
        zs[tid] = 1.0f / (6.0f * z);
    }
    __syncthreads();

    // write normalized per-head partial as half2 (coalesced)
    __half2* dst = g_part_h + (((size_t)(h * BATCH + b)) * MTEST + mt * 32) * (NCLASS / 2);
    for (int i = tid; i < 32 * (NCLASS / 2); i += 512) {
        int q = i >> 8, c2 = i & 255;
        float z = zs[q];
        float v0 = hist[(2 * c2)     * HSTRIDE + q] * z;
        float v1 = hist[(2 * c2 + 1) * HSTRIDE + q] * z;
        dst[q * (NCLASS / 2) + c2] = __floats2half2_rn(v0, v1);
    }
}

// ---------------- kernel 4: sum heads (fp16 partials) + log, write [M,B,C] ----------------
__global__ void final_kernel(float* __restrict__ out)
{
    int i = blockIdx.x * blockDim.x + threadIdx.x;      // half2 index
    if (i >= (MTEST * BATCH * NCLASS) / 2) return;
    int c2 = i & 255;
    int bm = i >> 8;             // m*8 + b
    int b  = bm & 7;
    int m  = bm >> 3;
    size_t pi = ((size_t)(b * MTEST) + m) * (NCLASS / 2) + c2;
    float vx = 0.f, vy = 0.f;
#pragma unroll
    for (int hh = 0; hh < NHEADS; hh++) {
        float2 p = __half22float2(g_part_h[(size_t)hh * (BATCH * MTEST * NCLASS / 2) + pi]);
        vx += p.x; vy += p.y;
    }
    float2 o;
    o.x = logf(fmaxf(vx, 1e-5f) + 3e-5f);
    o.y = logf(fmaxf(vy, 1e-5f) + 3e-5f);
    *((float2*)out + ((size_t)(m * 8 + b)) * 256 + c2) = o;
}

// ---------------- launch ----------------
extern "C" void kernel_launch(void* const* d_in, const int* in_sizes, int n_in,
                              void* d_out, int out_size)
{
    const float* train   = (const float*)d_in[0];
    const float* test    = (const float*)d_in[1];
    const int*   targets = (const int*)  d_in[2];
    const float* Wq      = (const float*)d_in[3];
    const float* bq      = (const float*)d_in[4];
    const float* Wk      = (const float*)d_in[5];
    const float* bk      = (const float*)d_in[6];
    float* out = (float*)d_out;

    cudaFuncSetAttribute(attn_kernel,
                         cudaFuncAttributeMaxDynamicSharedMemorySize, SMEM_BYTES);

    prep_kernel<<<2 * DATTN, 128>>>(Wq, Wk);
    sort_kernel<<<BATCH, 512>>>(targets);

    proj_kernel<<<dim3(192, DATTN / 128), 256>>>(train, test, bq, bk);

    attn_kernel<<<dim3(MTEST / 32, BATCH, NHEADS), 512, SMEM_BYTES>>>();

    final_kernel<<<(MTEST * BATCH * NCLASS / 2 + 255) / 256, 256>>>(out);
}